// round 1
// baseline (speedup 1.0000x reference)
#include <cuda_runtime.h>
#include <math.h>

// Problem constants (fixed shapes per reference)
#define LAYERS 4
#define D_     128
#define N_     2048      // B*K = 64*32
#define TWON   4096      // 2*N
#define TM     64
#define TN     128
#define PADW   132       // row stride in words: D + 4 (keeps float4 16B-aligned, conflict-free)
#define INV_T  5.0f      // 1/0.2
#define EPS    1e-12f

// Scratch (device globals — no allocations allowed)
__device__ float g_z[LAYERS * TWON * D_];   // normalized reps, row-major [layer][row][d]  (8 MB)
__device__ float g_lp[LAYERS * TWON];       // per-row loss partial: log(denom) - pos/T

// ---------------------------------------------------------------------------
// Kernel 1: L2-normalize emb_i / emb_j into g_z.  One warp per row.
// ---------------------------------------------------------------------------
__global__ void normalize_kernel(const float* __restrict__ emb_i,
                                 const float* __restrict__ emb_j) {
    int warp = (blockIdx.x * blockDim.x + threadIdx.x) >> 5;
    int lane = threadIdx.x & 31;
    if (warp >= LAYERS * TWON) return;
    int layer = warp >> 12;          // / TWON
    int row   = warp & (TWON - 1);   // % TWON

    const float* src = (row < N_)
        ? (emb_i + ((size_t)layer * N_ + row) * D_)
        : (emb_j + ((size_t)layer * N_ + (row - N_)) * D_);

    float4 v = ((const float4*)src)[lane];
    float s = v.x * v.x + v.y * v.y + v.z * v.z + v.w * v.w;
    #pragma unroll
    for (int o = 16; o > 0; o >>= 1) s += __shfl_xor_sync(0xffffffffu, s, o);

    float nrm = sqrtf(s);
    float inv = 1.0f / fmaxf(nrm, EPS);
    float4 o4 = make_float4(v.x * inv, v.y * inv, v.z * inv, v.w * inv);
    ((float4*)(g_z + ((size_t)layer * TWON + row) * D_))[lane] = o4;
}

// ---------------------------------------------------------------------------
// Kernel 2: fused Gram + exp + row reduction.
// Block: 256 threads (16x16).  Tile: TM=64 rows x TN=128 cols, full D=128 in smem.
// Per-thread micro-tile 4x8: rows {ty+16i}, cols {tx+16j}.
// ---------------------------------------------------------------------------
extern __shared__ float smem_dyn[];

__global__ void __launch_bounds__(256, 2) sim_kernel() {
    float* As = smem_dyn;                 // [TM][PADW]
    float* Bs = smem_dyn + TM * PADW;     // [TN][PADW]

    int layer   = blockIdx.x >> 6;        // 64 row-tiles per layer
    int rt      = blockIdx.x & 63;
    int rowBase = rt * TM;
    const float* __restrict__ Z = g_z + (size_t)layer * TWON * D_;

    int tid = threadIdx.x;
    int tx  = tid & 15;
    int ty  = tid >> 4;

    // Load A tile: 64 rows x 128 floats. One warp per row-slice (32 float4 per row).
    {
        int r0 = tid >> 5, lane = tid & 31;
        #pragma unroll
        for (int p = 0; p < TM / 8; ++p) {
            int r = p * 8 + r0;
            float4 v = ((const float4*)(Z + (size_t)(rowBase + r) * D_))[lane];
            float* dst = As + r * PADW + lane * 4;
            dst[0] = v.x; dst[1] = v.y; dst[2] = v.z; dst[3] = v.w;
        }
    }

    float denom[4] = {0.f, 0.f, 0.f, 0.f};
    float posv[4]  = {0.f, 0.f, 0.f, 0.f};

    for (int ct = 0; ct < TWON / TN; ++ct) {
        __syncthreads();
        // Load B tile: 128 rows x 128 floats
        {
            int r0 = tid >> 5, lane = tid & 31;
            int colBase = ct * TN;
            #pragma unroll
            for (int p = 0; p < TN / 8; ++p) {
                int r = p * 8 + r0;
                float4 v = ((const float4*)(Z + (size_t)(colBase + r) * D_))[lane];
                float* dst = Bs + r * PADW + lane * 4;
                dst[0] = v.x; dst[1] = v.y; dst[2] = v.z; dst[3] = v.w;
            }
        }
        __syncthreads();

        float acc[4][8];
        #pragma unroll
        for (int i = 0; i < 4; ++i)
            #pragma unroll
            for (int j = 0; j < 8; ++j) acc[i][j] = 0.f;

        const float* Ap = As + ty * PADW;
        const float* Bp = Bs + tx * PADW;
        #pragma unroll 2
        for (int k4 = 0; k4 < D_ / 4; ++k4) {
            float4 a[4], b[8];
            #pragma unroll
            for (int i = 0; i < 4; ++i)
                a[i] = *(const float4*)(Ap + (16 * i) * PADW + 4 * k4);
            #pragma unroll
            for (int j = 0; j < 8; ++j)
                b[j] = *(const float4*)(Bp + (16 * j) * PADW + 4 * k4);
            #pragma unroll
            for (int i = 0; i < 4; ++i)
                #pragma unroll
                for (int j = 0; j < 8; ++j) {
                    acc[i][j] += a[i].x * b[j].x;
                    acc[i][j] += a[i].y * b[j].y;
                    acc[i][j] += a[i].z * b[j].z;
                    acc[i][j] += a[i].w * b[j].w;
                }
        }

        // Consume tile: exp into denominator (excluding diagonal), capture positive.
        #pragma unroll
        for (int i = 0; i < 4; ++i) {
            int row  = rowBase + ty + 16 * i;
            int prow = row ^ N_;               // positive column index
            #pragma unroll
            for (int j = 0; j < 8; ++j) {
                int col = ct * TN + tx + 16 * j;
                float s = acc[i][j];
                float e = __expf(s * INV_T);
                denom[i] += (col != row)  ? e : 0.f;
                posv[i]  += (col == prow) ? s : 0.f;
            }
        }
    }

    // Reduce across tx (16 lanes of the half-warp); lane = (ty&1)*16 + tx.
    #pragma unroll
    for (int i = 0; i < 4; ++i) {
        float d = denom[i], p = posv[i];
        #pragma unroll
        for (int o = 8; o > 0; o >>= 1) {
            d += __shfl_xor_sync(0xffffffffu, d, o);
            p += __shfl_xor_sync(0xffffffffu, p, o);
        }
        if (tx == 0) {
            int row = rowBase + ty + 16 * i;
            g_lp[layer * TWON + row] = logf(d) - p * INV_T;
        }
    }
}

// ---------------------------------------------------------------------------
// Kernel 3: deterministic final reduction with joint_valid mask.
// ---------------------------------------------------------------------------
__global__ void finalize_kernel(const float* __restrict__ joint_valid,
                                float* __restrict__ out) {
    __shared__ float s1[256];
    __shared__ float s2[256];
    int tid = threadIdx.x;

    float total = 0.f;
    for (int idx = tid; idx < LAYERS * TWON; idx += 256) {
        int row = idx & (TWON - 1);
        float m = joint_valid[row & (N_ - 1)];   // row % N  (both halves share mask)
        total += g_lp[idx] * m;
    }
    float an = 0.f;
    for (int idx = tid; idx < N_; idx += 256) an += joint_valid[idx];

    s1[tid] = total;
    s2[tid] = an;
    __syncthreads();
    for (int s = 128; s > 0; s >>= 1) {
        if (tid < s) { s1[tid] += s1[tid + s]; s2[tid] += s2[tid + s]; }
        __syncthreads();
    }
    if (tid == 0) out[0] = s1[0] / (2.0f * s2[0]);
}

// ---------------------------------------------------------------------------
extern "C" void kernel_launch(void* const* d_in, const int* in_sizes, int n_in,
                              void* d_out, int out_size) {
    const float* emb_i       = (const float*)d_in[0];
    const float* emb_j       = (const float*)d_in[1];
    const float* joint_valid = (const float*)d_in[2];
    float* out = (float*)d_out;

    (void)in_sizes; (void)n_in; (void)out_size;

    // Dynamic smem for sim_kernel: (TM + TN) * PADW floats = 101376 bytes.
    static const int SIM_SMEM = (TM + TN) * PADW * (int)sizeof(float);
    cudaFuncSetAttribute(sim_kernel, cudaFuncAttributeMaxDynamicSharedMemorySize, SIM_SMEM);

    // 1) normalize: one warp per row, 16384 rows -> 2048 blocks of 256.
    normalize_kernel<<<(LAYERS * TWON) / 8, 256>>>(emb_i, emb_j);

    // 2) fused Gram + softmax-denominator: 4 layers * 64 row tiles = 256 blocks.
    sim_kernel<<<LAYERS * 64, 256, SIM_SMEM>>>();

    // 3) final masked reduction -> scalar.
    finalize_kernel<<<1, 256>>>(joint_valid, out);
}

// round 3
// speedup vs baseline: 6.1209x; 6.1209x over previous
#include <cuda_runtime.h>
#include <cuda_bf16.h>
#include <math.h>
#include <stdint.h>

// Problem constants
#define LAYERS 4
#define D_     128
#define N_     2048
#define TWON   4096
#define INV_T  5.0f
#define EPS    1e-12f
#define C_EX2  7.21347520444481703076f   // (1/T) * log2(e)

#define NCHUNK 32          // 4096 / 128 cols per chunk
#define CHUNK  128
#define SROW   136         // smem row stride in bf16 (272 bytes)
#define SROWB  272
#define TILEB  (128 * SROWB)   // one 128x128 bf16 tile in smem = 34816 B

// Scratch
__device__ __align__(256) __nv_bfloat16 g_zb[LAYERS * TWON * D_];
__device__ float g_lp[LAYERS * TWON];

// ---------------------------------------------------------------------------
// Helpers
// ---------------------------------------------------------------------------
__device__ __forceinline__ uint32_t smem_u32(const void* p) {
    uint32_t a;
    asm("{ .reg .u64 t; cvta.to.shared.u64 t, %1; cvt.u32.u64 %0, t; }" : "=r"(a) : "l"(p));
    return a;
}
__device__ __forceinline__ float ex2f(float x) {
    float r; asm("ex2.approx.ftz.f32 %0, %1;" : "=f"(r) : "f"(x)); return r;
}
#define CP_ASYNC16(dst, src) \
    asm volatile("cp.async.cg.shared.global [%0], [%1], 16;" :: "r"(dst), "l"(src))
#define CP_COMMIT() asm volatile("cp.async.commit_group;" ::: "memory")
#define CP_WAIT(n)  asm volatile("cp.async.wait_group %0;" :: "n"(n) : "memory")

__device__ __forceinline__ void ldsm4(uint32_t* r, uint32_t addr) {
    asm volatile("ldmatrix.sync.aligned.m8n8.x4.shared.b16 {%0,%1,%2,%3}, [%4];"
                 : "=r"(r[0]), "=r"(r[1]), "=r"(r[2]), "=r"(r[3]) : "r"(addr));
}
__device__ __forceinline__ void mma_bf16(float* c, const uint32_t* a, const uint32_t* b) {
    asm volatile(
        "mma.sync.aligned.m16n8k16.row.col.f32.bf16.bf16.f32 "
        "{%0,%1,%2,%3}, {%4,%5,%6,%7}, {%8,%9}, {%0,%1,%2,%3};"
        : "+f"(c[0]), "+f"(c[1]), "+f"(c[2]), "+f"(c[3])
        : "r"(a[0]), "r"(a[1]), "r"(a[2]), "r"(a[3]), "r"(b[0]), "r"(b[1]));
}

// ---------------------------------------------------------------------------
// Kernel 1: L2-normalize -> bf16. One warp per row.
// ---------------------------------------------------------------------------
__global__ void norm_bf16_kernel(const float* __restrict__ emb_i,
                                 const float* __restrict__ emb_j) {
    int warp = (blockIdx.x * blockDim.x + threadIdx.x) >> 5;
    int lane = threadIdx.x & 31;
    if (warp >= LAYERS * TWON) return;
    int layer = warp >> 12;
    int row   = warp & (TWON - 1);

    const float* src = (row < N_)
        ? (emb_i + ((size_t)layer * N_ + row) * D_)
        : (emb_j + ((size_t)layer * N_ + (row - N_)) * D_);

    float4 v = ((const float4*)src)[lane];
    float s = v.x * v.x + v.y * v.y + v.z * v.z + v.w * v.w;
    #pragma unroll
    for (int o = 16; o > 0; o >>= 1) s += __shfl_xor_sync(0xffffffffu, s, o);

    float inv = 1.0f / fmaxf(sqrtf(s), EPS);
    __nv_bfloat16 h0 = __float2bfloat16(v.x * inv);
    __nv_bfloat16 h1 = __float2bfloat16(v.y * inv);
    __nv_bfloat16 h2 = __float2bfloat16(v.z * inv);
    __nv_bfloat16 h3 = __float2bfloat16(v.w * inv);
    uint2 u;
    u.x = (uint32_t)__bfloat16_as_ushort(h0) | ((uint32_t)__bfloat16_as_ushort(h1) << 16);
    u.y = (uint32_t)__bfloat16_as_ushort(h2) | ((uint32_t)__bfloat16_as_ushort(h3) << 16);
    ((uint2*)(g_zb + ((size_t)layer * TWON + row) * D_))[lane] = u;
}

// ---------------------------------------------------------------------------
// Kernel 2: mma.sync fused Gram + exp + row reduction.
// Grid = LAYERS*32 CTAs; block = 256 (8 warps, 2x4 warp grid).
// M-tile = 128 rows (A in smem, loaded once), B streamed in 128-col chunks,
// double-buffered via cp.async. Accumulators in registers.
// ---------------------------------------------------------------------------
extern __shared__ char dsm[];

__device__ __forceinline__ void load_tile(const __nv_bfloat16* Z, int rowBase,
                                          uint32_t base, int tid) {
    #pragma unroll
    for (int i = 0; i < 8; ++i) {
        int idx = i * 256 + tid;           // 2048 16B-segments
        int r = idx >> 4, sc = idx & 15;
        const char* src = (const char*)(Z + (size_t)(rowBase + r) * D_) + sc * 16;
        CP_ASYNC16(base + r * SROWB + sc * 16, src);
    }
}

__global__ void __launch_bounds__(256, 1) sim_mma_kernel() {
    __shared__ float red_d[2][4][64];
    __shared__ float red_g[2][4][64];
    __shared__ float red_p[2][4][64];

    int tid  = threadIdx.x;
    int wid  = tid >> 5;
    int lane = tid & 31;
    int warpRow = wid >> 2;    // 0..1
    int warpCol = wid & 3;     // 0..3

    int layer   = blockIdx.x >> 5;
    int tile    = blockIdx.x & 31;
    int rowBase = tile * CHUNK;
    const __nv_bfloat16* Z = g_zb + (size_t)layer * TWON * D_;

    uint32_t sb = (smem_u32(dsm) + 1023) & ~1023u;
    uint32_t aBase = sb;
    uint32_t bBase[2] = { sb + TILEB, sb + 2 * TILEB };

    // Prologue: A tile + B chunk 0 (group 0)
    load_tile(Z, rowBase, aBase, tid);
    load_tile(Z, 0, bBase[0], tid);
    CP_COMMIT();

    // ldmatrix per-lane address components
    uint32_t laneA = (uint32_t)((lane & 7) * SROWB + ((lane >> 3) & 1) * (8 * SROWB)
                                + ((lane >> 4) & 1) * 16);
    uint32_t laneB = (uint32_t)((lane & 7) * SROWB + ((lane >> 3) & 1) * 16
                                + ((lane >> 4) & 1) * (8 * SROWB));
    uint32_t aAddr = aBase + (uint32_t)(warpRow * 64 * SROWB) + laneA;
    uint32_t bAddr0 = bBase[0] + (uint32_t)(warpCol * 32 * SROWB) + laneB;
    uint32_t bAddr1 = bBase[1] + (uint32_t)(warpCol * 32 * SROWB) + laneB;

    float acc[4][4][4];
    #pragma unroll
    for (int mt = 0; mt < 4; ++mt)
        #pragma unroll
        for (int nt = 0; nt < 4; ++nt)
            #pragma unroll
            for (int ci = 0; ci < 4; ++ci) acc[mt][nt][ci] = 0.f;

    float dsum[8], sdg[8], sps[8];
    #pragma unroll
    for (int i = 0; i < 8; ++i) { dsum[i] = 0.f; sdg[i] = 0.f; sps[i] = 0.f; }

    // Per-thread row/col constants
    int rowT = rowBase + warpRow * 64 + (lane >> 2);   // + mt*16 + 8*hi
    int colT = warpCol * 32 + (lane & 3) * 2;          // + nt*8 + (ci&1) + cb

    int diagChunk = tile;
    int posChunk  = tile ^ (N_ / CHUNK);               // tile ^ 16

    for (int ct = 0; ct < NCHUNK; ++ct) {
        if (ct + 1 < NCHUNK) {
            load_tile(Z, (ct + 1) * CHUNK, bBase[(ct + 1) & 1], tid);
            CP_COMMIT();
            CP_WAIT(1);
        } else {
            CP_WAIT(0);
        }
        __syncthreads();

        uint32_t bA = (ct & 1) ? bAddr1 : bAddr0;

        // MMA: K=128 in 8 k-tiles of 16
        #pragma unroll 2
        for (int kt = 0; kt < 8; ++kt) {
            uint32_t aF[4][4];
            uint32_t bF[4][2];
            #pragma unroll
            for (int mt = 0; mt < 4; ++mt)
                ldsm4(aF[mt], aAddr + (uint32_t)(mt * 16 * SROWB + kt * 32));
            #pragma unroll
            for (int np = 0; np < 2; ++np) {
                uint32_t t[4];
                ldsm4(t, bA + (uint32_t)(np * 16 * SROWB + kt * 32));
                bF[2 * np][0] = t[0]; bF[2 * np][1] = t[1];
                bF[2 * np + 1][0] = t[2]; bF[2 * np + 1][1] = t[3];
            }
            #pragma unroll
            for (int mt = 0; mt < 4; ++mt)
                #pragma unroll
                for (int nt = 0; nt < 4; ++nt)
                    mma_bf16(acc[mt][nt], aF[mt], bF[nt]);
        }

        // Epilogue: exp-accumulate; capture diag/pos only in the 2 relevant chunks
        int cb = ct * CHUNK;
        bool chk = (ct == diagChunk) || (ct == posChunk);
        if (chk) {
            #pragma unroll
            for (int mt = 0; mt < 4; ++mt)
                #pragma unroll
                for (int nt = 0; nt < 4; ++nt)
                    #pragma unroll
                    for (int ci = 0; ci < 4; ++ci) {
                        float s = acc[mt][nt][ci];
                        int ri = mt * 2 + (ci >> 1);
                        int grow = rowT + mt * 16 + (ci >> 1) * 8;
                        int gcol = cb + colT + nt * 8 + (ci & 1);
                        dsum[ri] += ex2f(s * C_EX2);
                        if (gcol == grow)        sdg[ri] = s;
                        if (gcol == (grow ^ N_)) sps[ri] = s;
                        acc[mt][nt][ci] = 0.f;
                    }
        } else {
            #pragma unroll
            for (int mt = 0; mt < 4; ++mt)
                #pragma unroll
                for (int nt = 0; nt < 4; ++nt)
                    #pragma unroll
                    for (int ci = 0; ci < 4; ++ci) {
                        float s = acc[mt][nt][ci];
                        int ri = mt * 2 + (ci >> 1);
                        dsum[ri] += ex2f(s * C_EX2);
                        acc[mt][nt][ci] = 0.f;
                    }
        }
        __syncthreads();
    }

    // Reduce across lane&3 (cols within warp)
    #pragma unroll
    for (int ri = 0; ri < 8; ++ri) {
        #pragma unroll
        for (int o = 1; o <= 2; o <<= 1) {
            dsum[ri] += __shfl_xor_sync(0xffffffffu, dsum[ri], o);
            sdg[ri]  += __shfl_xor_sync(0xffffffffu, sdg[ri], o);
            sps[ri]  += __shfl_xor_sync(0xffffffffu, sps[ri], o);
        }
    }
    if ((lane & 3) == 0) {
        #pragma unroll
        for (int ri = 0; ri < 8; ++ri) {
            int mt = ri >> 1, hi = ri & 1;
            int rloc = mt * 16 + (lane >> 2) + 8 * hi;
            red_d[warpRow][warpCol][rloc] = dsum[ri];
            red_g[warpRow][warpCol][rloc] = sdg[ri];
            red_p[warpRow][warpCol][rloc] = sps[ri];
        }
    }
    __syncthreads();

    if (tid < 128) {
        int wr = tid >> 6, rl = tid & 63;
        float d = 0.f, sg = 0.f, sp = 0.f;
        #pragma unroll
        for (int wc = 0; wc < 4; ++wc) {
            d  += red_d[wr][wc][rl];
            sg += red_g[wr][wc][rl];
            sp += red_p[wr][wc][rl];
        }
        float denom = d - ex2f(sg * C_EX2);  // exclude diagonal
        g_lp[layer * TWON + rowBase + tid] = logf(denom) - sp * INV_T;
    }
}

// ---------------------------------------------------------------------------
// Kernel 3: deterministic final reduction with joint_valid mask.
// ---------------------------------------------------------------------------
__global__ void finalize_kernel(const float* __restrict__ joint_valid,
                                float* __restrict__ out) {
    __shared__ float s1[256];
    __shared__ float s2[256];
    int tid = threadIdx.x;

    float total = 0.f;
    for (int idx = tid; idx < LAYERS * TWON; idx += 256) {
        int row = idx & (TWON - 1);
        total += g_lp[idx] * joint_valid[row & (N_ - 1)];
    }
    float an = 0.f;
    for (int idx = tid; idx < N_; idx += 256) an += joint_valid[idx];

    s1[tid] = total;
    s2[tid] = an;
    __syncthreads();
    for (int s = 128; s > 0; s >>= 1) {
        if (tid < s) { s1[tid] += s1[tid + s]; s2[tid] += s2[tid + s]; }
        __syncthreads();
    }
    if (tid == 0) out[0] = s1[0] / (2.0f * s2[0]);
}

// ---------------------------------------------------------------------------
extern "C" void kernel_launch(void* const* d_in, const int* in_sizes, int n_in,
                              void* d_out, int out_size) {
    const float* emb_i       = (const float*)d_in[0];
    const float* emb_j       = (const float*)d_in[1];
    const float* joint_valid = (const float*)d_in[2];
    float* out = (float*)d_out;
    (void)in_sizes; (void)n_in; (void)out_size;

    // dynamic smem: 1KB align slack + A tile + 2 B buffers = 1024 + 3*34816
    const int SIM_SMEM = 1024 + 3 * TILEB;
    cudaFuncSetAttribute(sim_mma_kernel, cudaFuncAttributeMaxDynamicSharedMemorySize, SIM_SMEM);

    norm_bf16_kernel<<<(LAYERS * TWON) / 8, 256>>>(emb_i, emb_j);
    sim_mma_kernel<<<LAYERS * 32, 256, SIM_SMEM>>>();
    finalize_kernel<<<1, 256>>>(joint_valid, out);
}